// round 1
// baseline (speedup 1.0000x reference)
#include <cuda_runtime.h>
#include <math.h>
#include <float.h>

// Problem constants
#define BSZ   32768
#define SMC   4
#define DIN   256
#define LAT   8
#define NBINS 300
#define KPIX  1323
#define RCP   4

#define ROWS_TOTAL (SMC * BSZ + BSZ)   // 163840 softmax rows
#define ZP_ROWS    (SMC * BSZ)         // 131072

// Output layout (concatenated in reference return order)
#define ZP_OFF    ((size_t)0)
#define MEAN_OFF  ((size_t)SMC * BSZ * KPIX)                 // 173408256
#define MU_OFF    (MEAN_OFF + (size_t)BSZ * KPIX)            // 216760320
#define STD_OFF   (MU_OFF + (size_t)BSZ * LAT)               // 217022464

// ---------------------------------------------------------------------------
// Kernel 1: encoder — mu_h = x @ mu_w^T + mu_b ; std_h = softplus(x @ std_w^T + std_b)
// warp-per-row, weights staged in shared.
// ---------------------------------------------------------------------------
__global__ void __launch_bounds__(256) encoder_kernel(
    const float* __restrict__ x,
    const float* __restrict__ mu_w, const float* __restrict__ mu_b,
    const float* __restrict__ std_w, const float* __restrict__ std_b,
    float* __restrict__ muh, float* __restrict__ stdh)
{
    __shared__ float smw[LAT * DIN];
    __shared__ float ssw[LAT * DIN];
    __shared__ float smb[LAT];
    __shared__ float ssb[LAT];

    int tid = threadIdx.x;
    for (int i = tid; i < LAT * DIN; i += 256) {
        smw[i] = mu_w[i];
        ssw[i] = std_w[i];
    }
    if (tid < LAT) { smb[tid] = mu_b[tid]; ssb[tid] = std_b[tid]; }
    __syncthreads();

    int wid  = tid >> 5;
    int lane = tid & 31;
    int row  = blockIdx.x * 8 + wid;
    if (row >= BSZ) return;

    float xv[8];
#pragma unroll
    for (int j = 0; j < 8; j++)
        xv[j] = x[(size_t)row * DIN + lane + 32 * j];

#pragma unroll
    for (int l = 0; l < LAT; l++) {
        float am = 0.f, as = 0.f;
#pragma unroll
        for (int j = 0; j < 8; j++) {
            float xx = xv[j];
            am = fmaf(xx, smw[l * DIN + lane + 32 * j], am);
            as = fmaf(xx, ssw[l * DIN + lane + 32 * j], as);
        }
#pragma unroll
        for (int o = 16; o > 0; o >>= 1) {
            am += __shfl_xor_sync(0xffffffffu, am, o);
            as += __shfl_xor_sync(0xffffffffu, as, o);
        }
        if (lane == 0) {
            muh[(size_t)row * LAT + l] = am + smb[l];
            float t = as + ssb[l];
            // softplus, overflow-safe
            stdh[(size_t)row * LAT + l] = (t > 20.f) ? t : log1pf(expf(t));
        }
    }
}

// ---------------------------------------------------------------------------
// Kernel 2: persistent profile/softmax kernel.
// Each CTA stages B (K x 4), A (NBINS x 4), C (8 x 4) in shared once, then
// loops over rows: 131072 sampled rows (zp) + 32768 mean rows.
// ---------------------------------------------------------------------------
__device__ __forceinline__ float warpRedMax(float v) {
#pragma unroll
    for (int o = 16; o > 0; o >>= 1)
        v = fmaxf(v, __shfl_xor_sync(0xffffffffu, v, o));
    return v;
}
__device__ __forceinline__ float warpRedSum(float v) {
#pragma unroll
    for (int o = 16; o > 0; o >>= 1)
        v += __shfl_xor_sync(0xffffffffu, v, o);
    return v;
}

__global__ void __launch_bounds__(256) profile_kernel(
    const float* __restrict__ Bmat,     // (K, 4)
    const float* __restrict__ Amat,     // (NBINS, 4)
    const float* __restrict__ Cmat,     // (LAT, 4)
    const float* __restrict__ bbias,    // (NBINS, K)
    const float* __restrict__ eps,      // (S, B, LAT)
    const int*   __restrict__ labels,   // (B,)
    const float* __restrict__ muh,      // (B, LAT)
    const float* __restrict__ stdh,     // (B, LAT)
    float* __restrict__ zp,             // (S, B, K)
    float* __restrict__ meanp)          // (B, K)
{
    __shared__ float4 Bs[KPIX];
    __shared__ float  As[NBINS * RCP];
    __shared__ float  Cs[LAT * RCP];
    __shared__ float  red[40];

    int tid = threadIdx.x;

    // Stage B rows as float4 (K*R floats, rows of 4 -> aligned float4 loads)
    const float4* B4 = (const float4*)Bmat;
    for (int i = tid; i < KPIX; i += 256) Bs[i] = B4[i];
    for (int i = tid; i < NBINS * RCP; i += 256) As[i] = Amat[i];
    if (tid < LAT * RCP) Cs[tid] = Cmat[tid];
    __syncthreads();

    int wid  = tid >> 5;
    int lane = tid & 31;

    for (int row = blockIdx.x; row < ROWS_TOTAL; row += gridDim.x) {
        int bidx;
        float* out;
        bool is_mean;
        if (row < ZP_ROWS) {
            bidx = row & (BSZ - 1);
            out = zp + (size_t)row * KPIX;
            is_mean = false;
        } else {
            bidx = row - ZP_ROWS;
            out = meanp + (size_t)bidx * KPIX;
            is_mean = true;
        }

        int g = __ldg(labels + bidx);

        // h -> z = h @ C -> w = A[g] * z   (uniform across the block)
        float z0 = 0.f, z1 = 0.f, z2 = 0.f, z3 = 0.f;
        const float* mh = muh + (size_t)bidx * LAT;
        const float* sh = stdh + (size_t)bidx * LAT;
        const float* ep = eps + (size_t)row * LAT;   // valid only when !is_mean (eps idx = (s*B+bidx)*LAT = row*LAT)
#pragma unroll
        for (int d = 0; d < LAT; d++) {
            float hv = __ldg(mh + d);
            if (!is_mean) hv = fmaf(__ldg(sh + d), __ldg(ep + d), hv);
            z0 = fmaf(hv, Cs[d * 4 + 0], z0);
            z1 = fmaf(hv, Cs[d * 4 + 1], z1);
            z2 = fmaf(hv, Cs[d * 4 + 2], z2);
            z3 = fmaf(hv, Cs[d * 4 + 3], z3);
        }
        float w0 = As[g * 4 + 0] * z0;
        float w1 = As[g * 4 + 1] * z1;
        float w2 = As[g * 4 + 2] * z2;
        float w3 = As[g * 4 + 3] * z3;

        const float* bb = bbias + (size_t)g * KPIX;

        // Pass 1: logits + local max (values stay in registers)
        float e[6];
        float lmax = -FLT_MAX;
#pragma unroll
        for (int j = 0; j < 6; j++) {
            int k = tid + 256 * j;
            if (k < KPIX) {
                float4 bk = Bs[k];
                float l = __ldg(bb + k);
                l = fmaf(w0, bk.x, l);
                l = fmaf(w1, bk.y, l);
                l = fmaf(w2, bk.z, l);
                l = fmaf(w3, bk.w, l);
                e[j] = l;
                lmax = fmaxf(lmax, l);
            } else {
                e[j] = -FLT_MAX;
            }
        }

        // Block-reduce max
        lmax = warpRedMax(lmax);
        if (lane == 0) red[wid] = lmax;
        __syncthreads();
        if (wid == 0) {
            float t = (lane < 8) ? red[lane] : -FLT_MAX;
            t = warpRedMax(t);
            if (lane == 0) red[32] = t;
        }
        __syncthreads();
        float m = red[32];

        // Pass 2: exp + local sum
        float lsum = 0.f;
#pragma unroll
        for (int j = 0; j < 6; j++) {
            float v = __expf(e[j] - m);   // padded lanes: exp(-huge) -> 0
            e[j] = v;
            lsum += v;
        }
        lsum = warpRedSum(lsum);
        if (lane == 0) red[wid] = lsum;
        __syncthreads();
        if (wid == 0) {
            float t = (lane < 8) ? red[lane] : 0.f;
            t = warpRedSum(t);
            if (lane == 0) red[33] = t;
        }
        __syncthreads();
        float inv = __fdividef(1.f, red[33]);

        // Pass 3: scaled store (coalesced, stride-256)
#pragma unroll
        for (int j = 0; j < 6; j++) {
            int k = tid + 256 * j;
            if (k < KPIX) out[k] = e[j] * inv;
        }
    }
}

// ---------------------------------------------------------------------------
// Launch
// ---------------------------------------------------------------------------
extern "C" void kernel_launch(void* const* d_in, const int* in_sizes, int n_in,
                              void* d_out, int out_size)
{
    const float* x      = (const float*)d_in[0];
    const float* eps    = (const float*)d_in[1];
    const float* Amat   = (const float*)d_in[2];
    const float* Bmat   = (const float*)d_in[3];
    const float* Cmat   = (const float*)d_in[4];
    const float* bbias  = (const float*)d_in[5];
    const float* mu_w   = (const float*)d_in[6];
    const float* mu_b   = (const float*)d_in[7];
    const float* std_w  = (const float*)d_in[8];
    const float* std_b  = (const float*)d_in[9];
    const int*   labels = (const int*)d_in[10];

    float* out   = (float*)d_out;
    float* zp    = out + ZP_OFF;
    float* meanp = out + MEAN_OFF;
    float* muh   = out + MU_OFF;
    float* stdh  = out + STD_OFF;

    encoder_kernel<<<BSZ / 8, 256>>>(x, mu_w, mu_b, std_w, std_b, muh, stdh);
    profile_kernel<<<148 * 8, 256>>>(Bmat, Amat, Cmat, bbias, eps, labels,
                                     muh, stdh, zp, meanp);
}

// round 2
// speedup vs baseline: 1.5214x; 1.5214x over previous
#include <cuda_runtime.h>
#include <math.h>
#include <float.h>

// Problem constants
#define BSZ   32768
#define SMC   4
#define DIN   256
#define LAT   8
#define NBINS 300
#define KPIX  1323
#define RCP   4

// Output layout (concatenated in reference return order)
#define ZP_OFF    ((size_t)0)
#define MEAN_OFF  ((size_t)SMC * BSZ * KPIX)
#define MU_OFF    (MEAN_OFF + (size_t)BSZ * KPIX)
#define STD_OFF   (MU_OFF + (size_t)BSZ * LAT)

// ---------------------------------------------------------------------------
// Kernel 1: encoder — mu_h = x @ mu_w^T + mu_b ; std_h = softplus(x @ std_w^T + std_b)
// Persistent grid, warp-per-row, weights staged in shared once per CTA.
// ---------------------------------------------------------------------------
__global__ void __launch_bounds__(256) encoder_kernel(
    const float* __restrict__ x,
    const float* __restrict__ mu_w, const float* __restrict__ mu_b,
    const float* __restrict__ std_w, const float* __restrict__ std_b,
    float* __restrict__ muh, float* __restrict__ stdh)
{
    __shared__ float smw[LAT * DIN];
    __shared__ float ssw[LAT * DIN];
    __shared__ float smb[LAT];
    __shared__ float ssb[LAT];

    int tid = threadIdx.x;
    for (int i = tid; i < LAT * DIN; i += 256) {
        smw[i] = mu_w[i];
        ssw[i] = std_w[i];
    }
    if (tid < LAT) { smb[tid] = mu_b[tid]; ssb[tid] = std_b[tid]; }
    __syncthreads();

    int wid  = tid >> 5;
    int lane = tid & 31;

    for (int row = blockIdx.x * 8 + wid; row < BSZ; row += gridDim.x * 8) {
        float xv[8];
#pragma unroll
        for (int j = 0; j < 8; j++)
            xv[j] = x[(size_t)row * DIN + lane + 32 * j];

#pragma unroll
        for (int l = 0; l < LAT; l++) {
            float am = 0.f, as = 0.f;
#pragma unroll
            for (int j = 0; j < 8; j++) {
                float xx = xv[j];
                am = fmaf(xx, smw[l * DIN + lane + 32 * j], am);
                as = fmaf(xx, ssw[l * DIN + lane + 32 * j], as);
            }
#pragma unroll
            for (int o = 16; o > 0; o >>= 1) {
                am += __shfl_xor_sync(0xffffffffu, am, o);
                as += __shfl_xor_sync(0xffffffffu, as, o);
            }
            if (lane == 0) {
                muh[(size_t)row * LAT + l] = am + smb[l];
                float t = as + ssb[l];
                stdh[(size_t)row * LAT + l] = (t > 20.f) ? t : log1pf(expf(t));
            }
        }
    }
}

// ---------------------------------------------------------------------------
// Kernel 2: persistent profile/softmax kernel.
// One iteration = one batch element bidx = 5 softmax rows (4 samples + mean).
// B lives in registers (loop-invariant per thread). Bias loaded once per bidx.
// No max-subtraction (|logits| << 1 by construction), single sum reduction.
// ---------------------------------------------------------------------------
__device__ __forceinline__ float warpRedSum(float v) {
#pragma unroll
    for (int o = 16; o > 0; o >>= 1)
        v += __shfl_xor_sync(0xffffffffu, v, o);
    return v;
}

__global__ void __launch_bounds__(256, 2) profile_kernel(
    const float* __restrict__ Bmat,     // (K, 4)
    const float* __restrict__ Amat,     // (NBINS, 4)
    const float* __restrict__ Cmat,     // (LAT, 4)
    const float* __restrict__ bbias,    // (NBINS, K)
    const float* __restrict__ eps,      // (S, B, LAT)
    const int*   __restrict__ labels,   // (B,)
    const float* __restrict__ muh,      // (B, LAT)
    const float* __restrict__ stdh,     // (B, LAT)
    float* __restrict__ zp,             // (S, B, K)
    float* __restrict__ meanp)          // (B, K)
{
    __shared__ float4 As4[NBINS];
    __shared__ float  Cs[LAT * RCP];
    __shared__ float  red[8 * 5];
    __shared__ float  fin[5];

    int tid = threadIdx.x;
    const float4* A4 = (const float4*)Amat;
    for (int i = tid; i < NBINS; i += 256) As4[i] = A4[i];
    if (tid < LAT * RCP) Cs[tid] = Cmat[tid];
    __syncthreads();

    // Loop-invariant: this thread's 6 B rows, in registers.
    const float4* B4 = (const float4*)Bmat;
    float4 Bv[6];
#pragma unroll
    for (int j = 0; j < 6; j++) {
        int k = tid + 256 * j;
        Bv[j] = (k < KPIX) ? B4[k] : make_float4(0.f, 0.f, 0.f, 0.f);
    }

    int wid  = tid >> 5;
    int lane = tid & 31;

    for (int bidx = blockIdx.x; bidx < BSZ; bidx += gridDim.x) {
        int g = __ldg(labels + bidx);
        float4 a4 = As4[g];
        const float* bb = bbias + (size_t)g * KPIX;

        // w[r][i] = A[g][i] * (h_r @ C)[i] for the 5 rows (uniform across block)
        const float* mh = muh  + (size_t)bidx * LAT;
        const float* sh = stdh + (size_t)bidx * LAT;
        float w[5][4];
#pragma unroll
        for (int r = 0; r < 5; r++) {
            float z0 = 0.f, z1 = 0.f, z2 = 0.f, z3 = 0.f;
            const float* ep = eps + ((size_t)r * BSZ + bidx) * LAT;  // r<4 only
#pragma unroll
            for (int d = 0; d < LAT; d++) {
                float hv = __ldg(mh + d);
                if (r < 4) hv = fmaf(__ldg(sh + d), __ldg(ep + d), hv);
                z0 = fmaf(hv, Cs[d * 4 + 0], z0);
                z1 = fmaf(hv, Cs[d * 4 + 1], z1);
                z2 = fmaf(hv, Cs[d * 4 + 2], z2);
                z3 = fmaf(hv, Cs[d * 4 + 3], z3);
            }
            w[r][0] = a4.x * z0;
            w[r][1] = a4.y * z1;
            w[r][2] = a4.z * z2;
            w[r][3] = a4.w * z3;
        }

        // Single pass: logits -> exp -> local sums. Values stay in registers.
        float e[5][6];
        float lsum[5] = {0.f, 0.f, 0.f, 0.f, 0.f};
#pragma unroll
        for (int j = 0; j < 6; j++) {
            int k = tid + 256 * j;
            bool act = (k < KPIX);
            float bk = act ? __ldg(bb + k) : 0.f;
            float4 Bk = Bv[j];
#pragma unroll
            for (int r = 0; r < 5; r++) {
                float l = bk;
                l = fmaf(w[r][0], Bk.x, l);
                l = fmaf(w[r][1], Bk.y, l);
                l = fmaf(w[r][2], Bk.z, l);
                l = fmaf(w[r][3], Bk.w, l);
                float v = act ? __expf(l) : 0.f;
                e[r][j] = v;
                lsum[r] += v;
            }
        }

        // Block-reduce the 5 sums.
#pragma unroll
        for (int r = 0; r < 5; r++) lsum[r] = warpRedSum(lsum[r]);
        if (lane == 0) {
#pragma unroll
            for (int r = 0; r < 5; r++) red[wid * 5 + r] = lsum[r];
        }
        __syncthreads();
        if (tid < 5) {
            float s = 0.f;
#pragma unroll
            for (int w8 = 0; w8 < 8; w8++) s += red[w8 * 5 + tid];
            fin[tid] = s;
        }
        __syncthreads();

        // Scaled stores, coalesced stride-256.
#pragma unroll
        for (int r = 0; r < 5; r++) {
            float inv = __fdividef(1.f, fin[r]);
            float* out = (r < 4) ? zp + ((size_t)r * BSZ + bidx) * KPIX
                                 : meanp + (size_t)bidx * KPIX;
#pragma unroll
            for (int j = 0; j < 6; j++) {
                int k = tid + 256 * j;
                if (k < KPIX) out[k] = e[r][j] * inv;
            }
        }
        // No extra barrier needed: red is only read between the two syncs above,
        // and fin is only written between them; the next iteration's first
        // __syncthreads orders everything.
    }
}

// ---------------------------------------------------------------------------
// Launch
// ---------------------------------------------------------------------------
extern "C" void kernel_launch(void* const* d_in, const int* in_sizes, int n_in,
                              void* d_out, int out_size)
{
    const float* x      = (const float*)d_in[0];
    const float* eps    = (const float*)d_in[1];
    const float* Amat   = (const float*)d_in[2];
    const float* Bmat   = (const float*)d_in[3];
    const float* Cmat   = (const float*)d_in[4];
    const float* bbias  = (const float*)d_in[5];
    const float* mu_w   = (const float*)d_in[6];
    const float* mu_b   = (const float*)d_in[7];
    const float* std_w  = (const float*)d_in[8];
    const float* std_b  = (const float*)d_in[9];
    const int*   labels = (const int*)d_in[10];

    float* out   = (float*)d_out;
    float* zp    = out + ZP_OFF;
    float* meanp = out + MEAN_OFF;
    float* muh   = out + MU_OFF;
    float* stdh  = out + STD_OFF;

    encoder_kernel<<<592, 256>>>(x, mu_w, mu_b, std_w, std_b, muh, stdh);
    profile_kernel<<<296, 256>>>(Bmat, Amat, Cmat, bbias, eps, labels,
                                 muh, stdh, zp, meanp);
}

// round 3
// speedup vs baseline: 1.6806x; 1.1046x over previous
#include <cuda_runtime.h>
#include <math.h>
#include <float.h>

// Problem constants
#define BSZ   32768
#define SMC   4
#define DIN   256
#define LAT   8
#define NBINS 300
#define KPIX  1323
#define RCP   4

// Output layout (concatenated in reference return order)
#define ZP_OFF    ((size_t)0)
#define MEAN_OFF  ((size_t)SMC * BSZ * KPIX)
#define MU_OFF    (MEAN_OFF + (size_t)BSZ * KPIX)
#define STD_OFF   (MU_OFF + (size_t)BSZ * LAT)

#define NWORK 256          // worker threads (8 warps)
#define NTHR  288          // + 1 producer warp
#define GRID  296          // 2 CTAs/SM * 148 SMs, persistent

// ---------------------------------------------------------------------------
// Fused persistent kernel, warp-specialized:
//   warps 0..7 (256 thr): per-pixel logits -> exp -> sum -> normalized store
//   warp 8 (producer):    encoder (x@W^T+b, softplus), mu/std outputs,
//                         w[5][4] = A[g] * (h_r @ C) for next bidx (pipelined)
// ---------------------------------------------------------------------------
__global__ void __launch_bounds__(NTHR, 2) fused_kernel(
    const float* __restrict__ x,       // (B, DIN)
    const float* __restrict__ eps,     // (S, B, LAT)
    const float* __restrict__ Amat,    // (NBINS, R)
    const float* __restrict__ Bmat,    // (K, R)
    const float* __restrict__ Cmat,    // (LAT, R)
    const float* __restrict__ bbias,   // (NBINS, K)
    const float* __restrict__ mu_w,    // (LAT, DIN)
    const float* __restrict__ mu_b,    // (LAT,)
    const float* __restrict__ std_w,   // (LAT, DIN)
    const float* __restrict__ std_b,   // (LAT,)
    const int*   __restrict__ labels,  // (B,)
    float* __restrict__ zp,            // (S, B, K)
    float* __restrict__ meanp,         // (B, K)
    float* __restrict__ muh,           // (B, LAT)
    float* __restrict__ stdh)          // (B, LAT)
{
    __shared__ float  smw[LAT * DIN];   // mu weights
    __shared__ float  ssw[LAT * DIN];   // std weights
    __shared__ float  smb[LAT];
    __shared__ float  ssb[LAT];
    __shared__ float4 As4[NBINS];
    __shared__ float  Cs[LAT * RCP];
    __shared__ float4 wbuf[2][5];       // double-buffered w[5][4]
    __shared__ float  red[8 * 5];       // per-warp partial sums

    const int tid = threadIdx.x;

    // --- stage block-invariant data ---
    for (int i = tid; i < LAT * DIN; i += NTHR) { smw[i] = mu_w[i]; ssw[i] = std_w[i]; }
    {
        const float4* A4 = (const float4*)Amat;
        for (int i = tid; i < NBINS; i += NTHR) As4[i] = A4[i];
    }
    if (tid < LAT * RCP) Cs[tid] = Cmat[tid];
    if (tid < LAT) { smb[tid] = mu_b[tid]; ssb[tid] = std_b[tid]; }
    __syncthreads();

    if (tid < NWORK) {
        // =========================== WORKERS =============================
        const int wid  = tid >> 5;
        const int lane = tid & 31;

        // Loop-invariant: this thread's 6 B rows in registers.
        const float4* B4 = (const float4*)Bmat;
        float4 Bv[6];
#pragma unroll
        for (int j = 0; j < 6; j++) {
            int k = tid + 256 * j;
            Bv[j] = (k < KPIX) ? B4[k] : make_float4(0.f, 0.f, 0.f, 0.f);
        }

        // Prologue: bias for first bidx.
        float pb[6];
        {
            int b0 = blockIdx.x;
            int g  = __ldg(labels + b0);
            const float* bb = bbias + (size_t)g * KPIX;
#pragma unroll
            for (int j = 0; j < 6; j++) {
                int k = tid + 256 * j;
                pb[j] = (k < KPIX) ? __ldg(bb + k) : 0.f;
            }
        }
        asm volatile("bar.sync 0, %0;" :: "n"(NTHR));

        int t = 0;
        for (int b = blockIdx.x; b < BSZ; b += GRID, t++) {
            const int p = t & 1;

            // Prefetch next bidx's bias early (hidden behind pass1).
            int bn = b + GRID;
            float nb[6] = {0.f, 0.f, 0.f, 0.f, 0.f, 0.f};
            if (bn < BSZ) {
                int gn = __ldg(labels + bn);
                const float* bbn = bbias + (size_t)gn * KPIX;
#pragma unroll
                for (int j = 0; j < 6; j++) {
                    int k = tid + 256 * j;
                    if (k < KPIX) nb[j] = __ldg(bbn + k);
                }
            }

            // Read block-uniform w from producer's buffer.
            float w[5][4];
#pragma unroll
            for (int r = 0; r < 5; r++) {
                float4 v = wbuf[p][r];
                w[r][0] = v.x; w[r][1] = v.y; w[r][2] = v.z; w[r][3] = v.w;
            }

            // Pass 1: logits -> exp -> local sums (values stay in registers).
            float e[5][6];
            float lsum[5] = {0.f, 0.f, 0.f, 0.f, 0.f};
#pragma unroll
            for (int j = 0; j < 6; j++) {
                int  k   = tid + 256 * j;
                bool act = (k < KPIX);
                float bk = pb[j];
                float4 Bk = Bv[j];
#pragma unroll
                for (int r = 0; r < 5; r++) {
                    float l = fmaf(w[r][0], Bk.x, bk);
                    l = fmaf(w[r][1], Bk.y, l);
                    l = fmaf(w[r][2], Bk.z, l);
                    l = fmaf(w[r][3], Bk.w, l);
                    float v = act ? __expf(l) : 0.f;
                    e[r][j] = v;
                    lsum[r] += v;
                }
            }

            // Warp-reduce the 5 sums, one barrier, shuffle-broadcast inverses.
#pragma unroll
            for (int r = 0; r < 5; r++) {
#pragma unroll
                for (int o = 16; o > 0; o >>= 1)
                    lsum[r] += __shfl_xor_sync(0xffffffffu, lsum[r], o);
            }
            if (lane == 0) {
#pragma unroll
                for (int r = 0; r < 5; r++) red[wid * 5 + r] = lsum[r];
            }
            asm volatile("bar.sync 1, %0;" :: "n"(NWORK));
            float myinv = 0.f;
            if (lane < 5) {
                float s = 0.f;
#pragma unroll
                for (int w8 = 0; w8 < 8; w8++) s += red[w8 * 5 + lane];
                myinv = __fdividef(1.f, s);
            }
            float inv[5];
#pragma unroll
            for (int r = 0; r < 5; r++)
                inv[r] = __shfl_sync(0xffffffffu, myinv, r);

            // Scaled stores, coalesced stride-256.
#pragma unroll
            for (int r = 0; r < 5; r++) {
                float* out = (r < 4) ? zp + ((size_t)r * BSZ + b) * KPIX
                                     : meanp + (size_t)b * KPIX;
#pragma unroll
                for (int j = 0; j < 6; j++) {
                    int k = tid + 256 * j;
                    if (k < KPIX) out[k] = e[r][j] * inv[r];
                }
            }

#pragma unroll
            for (int j = 0; j < 6; j++) pb[j] = nb[j];
            asm volatile("bar.sync 0, %0;" :: "n"(NTHR));
        }
    } else {
        // =========================== PRODUCER ============================
        const int lane = tid & 31;

        auto produce = [&](int b, int p) {
            // Early independent loads.
            int g = __ldg(labels + b);
            float xv[8];
            const float* xr = x + (size_t)b * DIN;
#pragma unroll
            for (int j = 0; j < 8; j++) xv[j] = __ldg(xr + lane + 32 * j);

            float epv[8];
            int rr = lane >> 2;                 // row index for lanes < 20
            if (lane < 16) {                    // r = 0..3 need eps
                const float* ep = eps + ((size_t)rr * BSZ + b) * LAT;
#pragma unroll
                for (int d = 0; d < 8; d++) epv[d] = __ldg(ep + d);
            }

            // Encoder dot products: am/as[l] partials over this lane's 8 d's.
            float am[8], as[8];
#pragma unroll
            for (int l = 0; l < LAT; l++) { am[l] = 0.f; as[l] = 0.f; }
#pragma unroll
            for (int l = 0; l < LAT; l++) {
#pragma unroll
                for (int j = 0; j < 8; j++) {
                    float xx = xv[j];
                    am[l] = fmaf(xx, smw[l * DIN + lane + 32 * j], am[l]);
                    as[l] = fmaf(xx, ssw[l * DIN + lane + 32 * j], as[l]);
                }
            }
            // Butterfly reduce 16 values across the warp (replicated result).
#pragma unroll
            for (int o = 16; o > 0; o >>= 1) {
#pragma unroll
                for (int l = 0; l < LAT; l++) {
                    am[l] += __shfl_xor_sync(0xffffffffu, am[l], o);
                    as[l] += __shfl_xor_sync(0xffffffffu, as[l], o);
                }
            }

            float mu[8], sd[8];
#pragma unroll
            for (int l = 0; l < LAT; l++) {
                mu[l] = am[l] + smb[l];
                float tt = as[l] + ssb[l];
                sd[l] = (tt > 20.f) ? tt : log1pf(__expf(tt));
            }

            // Write mu_h / std_h outputs (replicated in regs; lane 0 stores).
            if (lane == 0) {
                float4* mo = (float4*)(muh + (size_t)b * LAT);
                float4* so = (float4*)(stdh + (size_t)b * LAT);
                mo[0] = make_float4(mu[0], mu[1], mu[2], mu[3]);
                mo[1] = make_float4(mu[4], mu[5], mu[6], mu[7]);
                so[0] = make_float4(sd[0], sd[1], sd[2], sd[3]);
                so[1] = make_float4(sd[4], sd[5], sd[6], sd[7]);
            }

            // w[r][i] = A[g][i] * (h_r @ C)[i]; lanes 0..19, lane = 4r + i.
            if (lane < 20) {
                int r = rr;            // lane >> 2
                int i = lane & 3;
                float z = 0.f;
#pragma unroll
                for (int d = 0; d < 8; d++) {
                    float h = mu[d];
                    if (r < 4) h = fmaf(sd[d], epv[d], h);
                    z = fmaf(h, Cs[d * 4 + i], z);
                }
                float a = ((const float*)As4)[g * 4 + i];
                ((float*)wbuf[p])[lane] = a * z;
            }
        };

        // Prologue: produce first bidx into buffer 0.
        produce(blockIdx.x, 0);
        asm volatile("bar.sync 0, %0;" :: "n"(NTHR));

        int t = 0;
        for (int b = blockIdx.x; b < BSZ; b += GRID, t++) {
            int bn = b + GRID;
            if (bn < BSZ) produce(bn, (t + 1) & 1);
            asm volatile("bar.sync 0, %0;" :: "n"(NTHR));
        }
    }
}

// ---------------------------------------------------------------------------
// Launch
// ---------------------------------------------------------------------------
extern "C" void kernel_launch(void* const* d_in, const int* in_sizes, int n_in,
                              void* d_out, int out_size)
{
    const float* x      = (const float*)d_in[0];
    const float* eps    = (const float*)d_in[1];
    const float* Amat   = (const float*)d_in[2];
    const float* Bmat   = (const float*)d_in[3];
    const float* Cmat   = (const float*)d_in[4];
    const float* bbias  = (const float*)d_in[5];
    const float* mu_w   = (const float*)d_in[6];
    const float* mu_b   = (const float*)d_in[7];
    const float* std_w  = (const float*)d_in[8];
    const float* std_b  = (const float*)d_in[9];
    const int*   labels = (const int*)d_in[10];

    float* out   = (float*)d_out;
    float* zp    = out + ZP_OFF;
    float* meanp = out + MEAN_OFF;
    float* muh   = out + MU_OFF;
    float* stdh  = out + STD_OFF;

    fused_kernel<<<GRID, NTHR>>>(x, eps, Amat, Bmat, Cmat, bbias,
                                 mu_w, mu_b, std_w, std_b, labels,
                                 zp, meanp, muh, stdh);
}